// round 2
// baseline (speedup 1.0000x reference)
#include <cuda_runtime.h>
#include <cstdint>

#define N_NODE 100000
#define N_EDGE 800000
#define EMB 128

// ---------------- static device scratch (allocation-free) ----------------
__device__ float g_h0[N_NODE * EMB];
__device__ float g_h1[N_NODE * EMB];
__device__ float g_n0[N_NODE * EMB];
__device__ float g_n1[N_NODE * EMB];
__device__ float g_E11[N_NODE * EMB];
__device__ float g_E01[N_NODE * EMB];
__device__ float g_E10[N_NODE * EMB];
__device__ float g_E00[N_NODE * EMB];
__device__ float g_a11[N_NODE * EMB];
__device__ float g_a01[N_NODE * EMB];
__device__ float g_a10[N_NODE * EMB];
__device__ float g_a00[N_NODE * EMB];
__device__ float g_T[N_NODE * 256];
__device__ float g_stats[1024];

// ---------------- tiny utility kernels ----------------
__global__ void k_zero(float* __restrict__ p, int n4) {
    float4 z = make_float4(0.f, 0.f, 0.f, 0.f);
    for (int i = blockIdx.x * blockDim.x + threadIdx.x; i < n4;
         i += gridDim.x * blockDim.x)
        reinterpret_cast<float4*>(p)[i] = z;
}

__global__ void k_copy(float* __restrict__ dst, const float* __restrict__ src, int n4) {
    for (int i = blockIdx.x * blockDim.x + threadIdx.x; i < n4;
         i += gridDim.x * blockDim.x)
        reinterpret_cast<float4*>(dst)[i] = reinterpret_cast<const float4*>(src)[i];
}

// a11 += 1.1 * h1   (GIN self-term prologue)
__global__ void k_gin_pre(float* __restrict__ a, const float* __restrict__ h, int n4) {
    for (int i = blockIdx.x * blockDim.x + threadIdx.x; i < n4;
         i += gridDim.x * blockDim.x) {
        float4 av = reinterpret_cast<float4*>(a)[i];
        float4 hv = reinterpret_cast<const float4*>(h)[i];
        av.x += 1.1f * hv.x; av.y += 1.1f * hv.y;
        av.z += 1.1f * hv.z; av.w += 1.1f * hv.w;
        reinterpret_cast<float4*>(a)[i] = av;
    }
}

__device__ __forceinline__ void red_add_v4(float* p, float4 v) {
    asm volatile("red.global.add.v4.f32 [%0], {%1,%2,%3,%4};"
                 :: "l"(p), "f"(v.x), "f"(v.y), "f"(v.z), "f"(v.w)
                 : "memory");
}

// ---------------- per-edge fused (ea @ We + be) scatter-add (layer-invariant) ----------------
__global__ void k_edge_embed(const float* __restrict__ ea, const int* __restrict__ dst,
                             const float* __restrict__ We, const float* __restrict__ be,
                             float* __restrict__ Eagg) {
    __shared__ float sW[16 * EMB];  // 8 KB
    for (int i = threadIdx.x; i < 16 * EMB; i += blockDim.x) sW[i] = We[i];
    __syncthreads();
    const int lane = threadIdx.x & 31;
    const int warp = (blockIdx.x * blockDim.x + threadIdx.x) >> 5;
    const int nwarp = (gridDim.x * blockDim.x) >> 5;
    const int c0 = lane * 4;
    const float4 bev = *reinterpret_cast<const float4*>(be + c0);
    for (int e = warp; e < N_EDGE; e += nwarp) {
        float av = (lane < 16) ? ea[(size_t)e * 16 + lane] : 0.f;
        float4 acc = bev;
#pragma unroll
        for (int k = 0; k < 16; k++) {
            float a = __shfl_sync(0xffffffffu, av, k);
            float4 w = *reinterpret_cast<const float4*>(sW + k * EMB + c0);
            acc.x += a * w.x; acc.y += a * w.y; acc.z += a * w.z; acc.w += a * w.w;
        }
        int d = dst[e];
        red_add_v4(Eagg + (size_t)d * EMB + c0, acc);
    }
}

// ---------------- per-layer node gather/scatter: agg[dst] += h[src] ----------------
__global__ void k_scatter(const float* __restrict__ h, const int* __restrict__ src,
                          const int* __restrict__ dst, float* __restrict__ agg) {
    const int lane = threadIdx.x & 31;
    const int warp = (blockIdx.x * blockDim.x + threadIdx.x) >> 5;
    if (warp >= N_EDGE) return;
    int s = __ldg(&src[warp]);
    int d = __ldg(&dst[warp]);
    float4 v = *reinterpret_cast<const float4*>(h + (size_t)s * EMB + lane * 4);
    red_add_v4(agg + (size_t)d * EMB + lane * 4, v);
}

// ---------------- 128x128x8 register-blocked SGEMM with fused epilogue ----------------
// C[M,N] = scale * maybe_relu(A[M,K] @ B[K,N] + bias[N])  (+= old C if accum)
__global__ __launch_bounds__(256) void k_sgemm(
    const float* __restrict__ A, const float* __restrict__ B,
    const float* __restrict__ bias, float* __restrict__ C,
    int M, int K, int N, float scale, int relu, int accum) {
    __shared__ float As[8][128];
    __shared__ float Bs[8][128];
    const int t = threadIdx.x;
    const int rowBase = blockIdx.y * 128;
    const int colBase = blockIdx.x * 128;
    const int arow = t >> 1, acol = (t & 1) * 4;
    const int brow = t >> 5, bcol = (t & 31) * 4;
    const int ty = t >> 4, tx = t & 15;

    float acc[8][8];
#pragma unroll
    for (int i = 0; i < 8; i++)
#pragma unroll
        for (int j = 0; j < 8; j++) acc[i][j] = 0.f;

    for (int k0 = 0; k0 < K; k0 += 8) {
        float4 av = make_float4(0.f, 0.f, 0.f, 0.f);
        int gr = rowBase + arow;
        if (gr < M) av = *reinterpret_cast<const float4*>(A + (size_t)gr * K + k0 + acol);
        As[acol + 0][arow] = av.x;
        As[acol + 1][arow] = av.y;
        As[acol + 2][arow] = av.z;
        As[acol + 3][arow] = av.w;
        *reinterpret_cast<float4*>(&Bs[brow][bcol]) =
            *reinterpret_cast<const float4*>(B + (size_t)(k0 + brow) * N + colBase + bcol);
        __syncthreads();
#pragma unroll
        for (int k = 0; k < 8; k++) {
            float ra[8], rb[8];
            *reinterpret_cast<float4*>(ra)     = *reinterpret_cast<float4*>(&As[k][ty * 8]);
            *reinterpret_cast<float4*>(ra + 4) = *reinterpret_cast<float4*>(&As[k][ty * 8 + 4]);
            *reinterpret_cast<float4*>(rb)     = *reinterpret_cast<float4*>(&Bs[k][tx * 8]);
            *reinterpret_cast<float4*>(rb + 4) = *reinterpret_cast<float4*>(&Bs[k][tx * 8 + 4]);
#pragma unroll
            for (int i = 0; i < 8; i++)
#pragma unroll
                for (int j = 0; j < 8; j++) acc[i][j] += ra[i] * rb[j];
        }
        __syncthreads();
    }

#pragma unroll
    for (int i = 0; i < 8; i++) {
        int gr = rowBase + ty * 8 + i;
        if (gr < M) {
#pragma unroll
            for (int j = 0; j < 8; j += 4) {
                int gc = colBase + tx * 8 + j;
                float4 v;
                v.x = acc[i][j + 0] + bias[gc + 0];
                v.y = acc[i][j + 1] + bias[gc + 1];
                v.z = acc[i][j + 2] + bias[gc + 2];
                v.w = acc[i][j + 3] + bias[gc + 3];
                if (relu) {
                    v.x = fmaxf(v.x, 0.f); v.y = fmaxf(v.y, 0.f);
                    v.z = fmaxf(v.z, 0.f); v.w = fmaxf(v.w, 0.f);
                }
                v.x *= scale; v.y *= scale; v.z *= scale; v.w *= scale;
                float* cp = C + (size_t)gr * N + gc;
                if (accum) {
                    float4 o = *reinterpret_cast<float4*>(cp);
                    v.x += o.x; v.y += o.y; v.z += o.z; v.w += o.w;
                }
                *reinterpret_cast<float4*>(cp) = v;
            }
        }
    }
}

// ---------------- BatchNorm (training-mode batch stats, biased variance) ----------------
__global__ void k_bn_stats(const float* __restrict__ X, int M, float* __restrict__ stats) {
    const int col = threadIdx.x & 127;
    const int rp = threadIdx.x >> 7;  // 0/1
    float s = 0.f, q = 0.f;
    for (int r = blockIdx.x * 2 + rp; r < M; r += gridDim.x * 2) {
        float v = X[(size_t)r * EMB + col];
        s += v; q += v * v;
    }
    atomicAdd(&stats[col], s);
    atomicAdd(&stats[EMB + col], q);
}

// stats layout: [0:256) type0 sum/sq, [256:512) type1 sum/sq,
//               [512:768) type0 a/b,  [768:1024) type1 a/b
__global__ void k_bn_finalize(float* __restrict__ stats, const float* __restrict__ gamma,
                              const float* __restrict__ beta, int layer, float invM) {
    int c = threadIdx.x;          // 256 threads
    int type = c >> 7, col = c & 127;
    float mu = stats[type * 256 + col] * invM;
    float var = stats[type * 256 + 128 + col] * invM - mu * mu;
    float a = gamma[layer * EMB + col] * rsqrtf(var + 1e-5f);
    float b = beta[layer * EMB + col] - a * mu;
    stats[512 + type * 256 + col] = a;
    stats[512 + type * 256 + 128 + col] = b;
}

__global__ void k_bn_apply(const float* __restrict__ X, float* __restrict__ Y, int M,
                           const float* __restrict__ coef, int relu) {
    const int n = M * EMB;
    for (int i = blockIdx.x * blockDim.x + threadIdx.x; i < n;
         i += gridDim.x * blockDim.x) {
        int col = i & 127;
        float v = coef[col] * X[i] + coef[128 + col];
        if (relu) v = fmaxf(v, 0.f);
        Y[i] = v;
    }
}

// ---------------- host orchestration ----------------
extern "C" void kernel_launch(void* const* d_in, const int* in_sizes, int n_in,
                              void* d_out, int out_size) {
    (void)in_sizes; (void)n_in; (void)out_size;
    const float* x0   = (const float*)d_in[0];
    const float* x1   = (const float*)d_in[1];
    const float* ea11 = (const float*)d_in[2];
    const float* ea10 = (const float*)d_in[3];
    const float* ea01 = (const float*)d_in[4];
    const float* ea00 = (const float*)d_in[5];
    const int*   ei11 = (const int*)d_in[6];
    const int*   ei10 = (const int*)d_in[7];
    const int*   ei01 = (const int*)d_in[8];
    const int*   ei00 = (const int*)d_in[9];
    const float* Wx  = (const float*)d_in[10];
    const float* bx  = (const float*)d_in[11];
    const float* We  = (const float*)d_in[12];
    const float* be  = (const float*)d_in[13];
    const float* gW1 = (const float*)d_in[14];
    const float* gb1 = (const float*)d_in[15];
    const float* gW2 = (const float*)d_in[16];
    const float* gb2 = (const float*)d_in[17];
    const float* W10 = (const float*)d_in[18];
    const float* b10 = (const float*)d_in[19];
    const float* W01 = (const float*)d_in[20];
    const float* b01 = (const float*)d_in[21];
    const float* W00 = (const float*)d_in[22];
    const float* b00 = (const float*)d_in[23];
    const float* gamma = (const float*)d_in[24];
    const float* beta  = (const float*)d_in[25];
    float* out = (float*)d_out;

    float *h0, *h1, *n0b, *n1b, *E11, *E01, *E10, *E00, *a11, *a01, *a10, *a00, *T, *stats;
    cudaGetSymbolAddress((void**)&h0,  g_h0);
    cudaGetSymbolAddress((void**)&h1,  g_h1);
    cudaGetSymbolAddress((void**)&n0b, g_n0);
    cudaGetSymbolAddress((void**)&n1b, g_n1);
    cudaGetSymbolAddress((void**)&E11, g_E11);
    cudaGetSymbolAddress((void**)&E01, g_E01);
    cudaGetSymbolAddress((void**)&E10, g_E10);
    cudaGetSymbolAddress((void**)&E00, g_E00);
    cudaGetSymbolAddress((void**)&a11, g_a11);
    cudaGetSymbolAddress((void**)&a01, g_a01);
    cudaGetSymbolAddress((void**)&a10, g_a10);
    cudaGetSymbolAddress((void**)&a00, g_a00);
    cudaGetSymbolAddress((void**)&T,   g_T);
    cudaGetSymbolAddress((void**)&stats, g_stats);

    const int n4 = N_NODE * EMB / 4;

    // Layer-invariant edge-embedding aggregates: E[d] = sum_{e->d} (ea[e]@We + be)
    k_zero<<<2048, 256>>>(E11, n4);
    k_zero<<<2048, 256>>>(E01, n4);
    k_zero<<<2048, 256>>>(E10, n4);
    k_zero<<<2048, 256>>>(E00, n4);
    k_edge_embed<<<2048, 256>>>(ea11, ei11 + N_EDGE, We, be, E11);
    k_edge_embed<<<2048, 256>>>(ea01, ei01 + N_EDGE, We, be, E01);
    k_edge_embed<<<2048, 256>>>(ea10, ei10 + N_EDGE, We, be, E10);
    k_edge_embed<<<2048, 256>>>(ea00, ei00 + N_EDGE, We, be, E00);

    // Input embeddings: h = x @ Wx + bx
    dim3 gEmb(1, (N_NODE + 127) / 128);
    k_sgemm<<<gEmb, 256>>>(x0, Wx, bx, h0, N_NODE, 256, EMB, 1.f, 0, 0);
    k_sgemm<<<gEmb, 256>>>(x1, Wx, bx, h1, N_NODE, 256, EMB, 1.f, 0, 0);

    const int sgrid = (N_EDGE * 32) / 256;  // 1 warp per edge
    float* cur0 = h0;
    float* cur1 = h1;

    for (int layer = 0; layer < 2; layer++) {
        float* o0 = (layer == 0) ? n0b : h0;
        float* o1 = (layer == 0) ? n1b : h1;

        // agg = E_agg, then agg[dst] += h[src]
        k_copy<<<2048, 256>>>(a11, E11, n4);
        k_copy<<<2048, 256>>>(a01, E01, n4);
        k_copy<<<2048, 256>>>(a10, E10, n4);
        k_copy<<<2048, 256>>>(a00, E00, n4);
        k_scatter<<<sgrid, 256>>>(cur1, ei11, ei11 + N_EDGE, a11);
        k_scatter<<<sgrid, 256>>>(cur0, ei01, ei01 + N_EDGE, a01);
        k_scatter<<<sgrid, 256>>>(cur1, ei10, ei10 + N_EDGE, a10);
        k_scatter<<<sgrid, 256>>>(cur0, ei00, ei00 + N_EDGE, a00);

        // GIN self term: a11 += (1+eps) * h1
        k_gin_pre<<<2048, 256>>>(a11, cur1, n4);

        // new1 = 0.5*relu(a11@gW1+gb1)@gW2+gb2*0.5 + 0.05*(a01@W01+b01)
        dim3 gT(2, (N_NODE + 127) / 128);
        k_sgemm<<<gT, 256>>>(a11, gW1, gb1, T, N_NODE, EMB, 256, 1.f, 1, 0);
        dim3 gO(1, (N_NODE + 127) / 128);
        k_sgemm<<<gO, 256>>>(T, gW2, gb2, o1, N_NODE, 256, EMB, 0.5f, 0, 0);
        k_sgemm<<<gO, 256>>>(a01, W01, b01, o1, N_NODE, EMB, EMB, 0.05f, 0, 1);
        // new0 = 0.05*(a10@W10+b10) + 0.05*(a00@W00+b00)
        k_sgemm<<<gO, 256>>>(a10, W10, b10, o0, N_NODE, EMB, EMB, 0.05f, 0, 0);
        k_sgemm<<<gO, 256>>>(a00, W00, b00, o0, N_NODE, EMB, EMB, 0.05f, 0, 1);

        // BatchNorm per node type; last layer writes straight to d_out
        k_zero<<<1, 128>>>(stats, 128);  // zero 512 floats of sums/sqsums
        k_bn_stats<<<1024, 256>>>(o0, N_NODE, stats);
        k_bn_stats<<<1024, 256>>>(o1, N_NODE, stats + 256);
        k_bn_finalize<<<1, 256>>>(stats, gamma, beta, layer, 1.f / N_NODE);
        int relu = (layer == 0) ? 1 : 0;
        float* dst0 = (layer == 0) ? o0 : out;
        float* dst1 = (layer == 0) ? o1 : out + (size_t)N_NODE * EMB;
        k_bn_apply<<<2048, 256>>>(o0, dst0, N_NODE, stats + 512, relu);
        k_bn_apply<<<2048, 256>>>(o1, dst1, N_NODE, stats + 768, relu);

        cur0 = o0;
        cur1 = o1;
    }
}